// round 8
// baseline (speedup 1.0000x reference)
#include <cuda_runtime.h>

#define NB 8
#define NN 10000
#define CI 16
#define TT 24
#define CO 32
#define NE 160000
#define BT 192   // NB*TT

// ---------------- device scratch (float4-typed => guaranteed 16B alignment) ----------------
__device__ float4 g_X0[(size_t)NN * BT * CI / 4];   // 122.88 MB  node-major layer-1 input
__device__ float4 g_Y1[(size_t)NN * BT * CO / 4];   // 245.76 MB  layer-1 output
__device__ int    g_cur[NN];
__device__ int    g_rowptr[NN + 1];
__device__ int    g_col[NE];
__device__ int    g_is64;

// ---------------- packed f32x2 helpers ----------------
__device__ __forceinline__ unsigned long long fma2(unsigned long long a,
                                                   unsigned long long b,
                                                   unsigned long long c) {
    unsigned long long d;
    asm("fma.rn.f32x2 %0, %1, %2, %3;" : "=l"(d) : "l"(a), "l"(b), "l"(c));
    return d;
}
__device__ __forceinline__ unsigned long long add2(unsigned long long a,
                                                   unsigned long long b) {
    unsigned long long d;
    asm("add.rn.f32x2 %0, %1, %2;" : "=l"(d) : "l"(a), "l"(b));
    return d;
}
__device__ __forceinline__ unsigned long long pk2(float x, float y) {
    unsigned long long r;
    asm("mov.b64 %0, {%1, %2};" : "=l"(r) : "f"(x), "f"(y));
    return r;
}
__device__ __forceinline__ float2 upk2(unsigned long long a) {
    float2 r;
    asm("mov.b64 {%0, %1}, %2;" : "=f"(r.x), "=f"(r.y) : "l"(a));
    return r;
}

__device__ __forceinline__ int edge_at(const void* ei, int idx) {
    if (g_is64) return (int)((const long long*)ei)[idx];
    return ((const int*)ei)[idx];
}

// ---------------- CSR prep: dtype detect + degree histogram + scan, one block ----------------
__global__ void __launch_bounds__(1024) k_prep(const void* ei) {
    __shared__ int sdeg[NN];
    __shared__ int ssum[1024];
    int tid = threadIdx.x;
    if (tid == 0) {
        const long long* p = (const long long*)ei;
        int ok64 = 1;
        for (int q = 0; q < 64; q++) {
            long long v = p[q];
            if (v < 0 || v >= NN) { ok64 = 0; break; }
        }
        g_is64 = ok64;
    }
    __syncthreads();
    for (int i = tid; i < NN; i += 1024) sdeg[i] = 0;
    __syncthreads();
    for (int e = tid; e < NE; e += 1024) atomicAdd(&sdeg[edge_at(ei, NE + e)], 1);
    __syncthreads();
    const int CHUNK = 10;
    int start = tid * CHUNK;
    int s = 0;
    for (int i = start; i < start + CHUNK && i < NN; i++) s += sdeg[i];
    ssum[tid] = s;
    __syncthreads();
    for (int off = 1; off < 1024; off <<= 1) {
        int v = (tid >= off) ? ssum[tid - off] : 0;
        __syncthreads();
        ssum[tid] += v;
        __syncthreads();
    }
    int run = ssum[tid] - s;
    for (int i = start; i < start + CHUNK && i < NN; i++) {
        g_rowptr[i] = run;
        g_cur[i] = 0;
        run += sdeg[i];
    }
    if (tid == 1023) g_rowptr[NN] = ssum[1023];
}

__global__ void k_fill(const void* __restrict__ ei) {
    int e = blockIdx.x * blockDim.x + threadIdx.x;
    if (e < NE) {
        int srcn = edge_at(ei, e);
        int d    = edge_at(ei, NE + e);
        int p = atomicAdd(&g_cur[d], 1);
        g_col[g_rowptr[d] + p] = srcn;
    }
}

// ---------------- input transpose: x[b][n][c][t] -> X0[n][b*T+t][c] ----------------
__global__ void k_transpose(const float* __restrict__ x) {
    __shared__ float s[BT * 17];
    int n = blockIdx.x;
    for (int j = threadIdx.x; j < NB * CI * TT; j += blockDim.x) {
        int b = j / (CI * TT);
        int r = j % (CI * TT);
        int c = r / TT;
        int t = r % TT;
        s[(b * TT + t) * 17 + c] = x[((size_t)(b * NN + n)) * (CI * TT) + r];
    }
    __syncthreads();
    float* X0f = (float*)g_X0;
    for (int j = threadIdx.x; j < BT * CI; j += blockDim.x) {
        X0f[(size_t)n * (BT * CI) + j] = s[(j >> 4) * 17 + (j & 15)];
    }
}

// ================= unified GIN layer: cooperative per-node tiled GEMM =================
// Block = 64 threads, handles 64 rows (blockIdx.y selects 64-row slab) of node blockIdx.x.
// Tensors selected DEVICE-SIDE (passing __device__ globals from host yields the host
// shadow object — on GB300 ATS that silently reads host memory; round-7 bug).
template<int KIN, int NHID, bool FINAL>
__global__ void __launch_bounds__(64) k_gin(
    const float* __restrict__ Wa, const float* __restrict__ ba,   // [KIN][NHID], [NHID]
    const float* __restrict__ Wb, const float* __restrict__ bb,   // [NHID][32], [32]
    float* __restrict__ outT)
{
    constexpr int NCH = NHID / 64;
    constexpr int KV  = KIN / 4;
    const float4* Xin = FINAL ? g_Y1 : g_X0;   // device-side symbol refs
    float4* Yout = g_Y1;

    __shared__ __align__(16) float s_act[KIN * 68];
    __shared__ __align__(16) float s_h[64 * 68];
    __shared__ __align__(16) float s_wa[KIN * 64];
    __shared__ __align__(16) float s_wb[64 * 32];
    __shared__ float s_ba[64];

    int n = blockIdx.x, tid = threadIdx.x;
    int rbase = blockIdx.y * 64;

    // ---- gather: thread owns row rbase+tid ----
    {
        float4 a[KV];
        size_t ro = ((size_t)n * BT + rbase + tid) * KV;
#pragma unroll
        for (int q = 0; q < KV; q++) a[q] = Xin[ro + q];
        int rs = g_rowptr[n], re = g_rowptr[n + 1];
        for (int e = rs; e < re; e++) {
            size_t so = ((size_t)g_col[e] * BT + rbase + tid) * KV;
#pragma unroll
            for (int q = 0; q < KV; q++) {
                float4 v = Xin[so + q];
                a[q].x += v.x; a[q].y += v.y; a[q].z += v.z; a[q].w += v.w;
            }
        }
#pragma unroll
        for (int q = 0; q < KV; q++) {
            s_act[(4 * q + 0) * 68 + tid] = a[q].x;
            s_act[(4 * q + 1) * 68 + tid] = a[q].y;
            s_act[(4 * q + 2) * 68 + tid] = a[q].z;
            s_act[(4 * q + 3) * 68 + tid] = a[q].w;
        }
    }

    // tile decode
    int t2 = tid & 31, khalf = tid >> 5;
    int r2 = (t2 >> 2) * 8, o2 = (t2 & 3) * 8;   // GEMM2 tile
    int r1 = (tid >> 3) * 8, j1 = (tid & 7) * 8; // GEMM1 tile

    // GEMM2 accumulators (8 outs x 4 rowpairs), persist across chunks
    unsigned long long acc2[8][4];
#pragma unroll
    for (int o = 0; o < 8; o++) {
        float bv = (khalf == 0) ? bb[o2 + o] : 0.f;
        unsigned long long bp = pk2(bv, bv);
#pragma unroll
        for (int p = 0; p < 4; p++) acc2[o][p] = bp;
    }

    for (int c = 0; c < NCH; c++) {
        // ---- stage chunk weights ----
        {
            const float4* Wav = (const float4*)Wa;   // [KIN][NHID/4]
            for (int i = tid; i < KIN * 16; i += 64) {
                int k = i >> 4, jv = i & 15;
                ((float4*)s_wa)[k * 16 + jv] = Wav[k * (NHID / 4) + c * 16 + jv];
            }
            const float4* Wbv = (const float4*)Wb;   // [NHID][8]
            for (int i = tid; i < 512; i += 64)
                ((float4*)s_wb)[i] = Wbv[c * 512 + i];
            s_ba[tid] = ba[c * 64 + tid];
        }
        __syncthreads();  // staging (+act on first iter) visible

        // ---- GEMM1: s_h[j][r] = relu(sum_k s_act[k][r]*s_wa[k][j] + ba[j]) ----
        {
            unsigned long long acc1[8][4];
#pragma unroll
            for (int o = 0; o < 8; o++) {
                float bv = s_ba[j1 + o];
                unsigned long long bp = pk2(bv, bv);
#pragma unroll
                for (int p = 0; p < 4; p++) acc1[o][p] = bp;
            }
#pragma unroll 4
            for (int k = 0; k < KIN; k++) {
                ulonglong2 a01 = *(const ulonglong2*)&s_act[k * 68 + r1];
                ulonglong2 a23 = *(const ulonglong2*)&s_act[k * 68 + r1 + 4];
                float4 wlo = *(const float4*)&s_wa[k * 64 + j1];
                float4 whi = *(const float4*)&s_wa[k * 64 + j1 + 4];
                unsigned long long ap[4] = {a01.x, a01.y, a23.x, a23.y};
                unsigned long long wd[8] = {pk2(wlo.x, wlo.x), pk2(wlo.y, wlo.y),
                                            pk2(wlo.z, wlo.z), pk2(wlo.w, wlo.w),
                                            pk2(whi.x, whi.x), pk2(whi.y, whi.y),
                                            pk2(whi.z, whi.z), pk2(whi.w, whi.w)};
#pragma unroll
                for (int o = 0; o < 8; o++)
#pragma unroll
                    for (int p = 0; p < 4; p++)
                        acc1[o][p] = fma2(ap[p], wd[o], acc1[o][p]);
            }
            // relu + write H tile
#pragma unroll
            for (int o = 0; o < 8; o++) {
                float2 p0 = upk2(acc1[o][0]), p1 = upk2(acc1[o][1]);
                float2 p2 = upk2(acc1[o][2]), p3 = upk2(acc1[o][3]);
                *(float4*)&s_h[(j1 + o) * 68 + r1] =
                    make_float4(fmaxf(p0.x, 0.f), fmaxf(p0.y, 0.f), fmaxf(p1.x, 0.f), fmaxf(p1.y, 0.f));
                *(float4*)&s_h[(j1 + o) * 68 + r1 + 4] =
                    make_float4(fmaxf(p2.x, 0.f), fmaxf(p2.y, 0.f), fmaxf(p3.x, 0.f), fmaxf(p3.y, 0.f));
            }
        }
        __syncthreads();  // H complete

        // ---- GEMM2: acc2 += s_h[k][r] * s_wb[k][o], k = khalf*32 .. +32 ----
        {
            int k0 = khalf * 32;
#pragma unroll 4
            for (int kk = 0; kk < 32; kk++) {
                int k = k0 + kk;
                ulonglong2 a01 = *(const ulonglong2*)&s_h[k * 68 + r2];
                ulonglong2 a23 = *(const ulonglong2*)&s_h[k * 68 + r2 + 4];
                float4 wlo = *(const float4*)&s_wb[k * 32 + o2];
                float4 whi = *(const float4*)&s_wb[k * 32 + o2 + 4];
                unsigned long long ap[4] = {a01.x, a01.y, a23.x, a23.y};
                unsigned long long wd[8] = {pk2(wlo.x, wlo.x), pk2(wlo.y, wlo.y),
                                            pk2(wlo.z, wlo.z), pk2(wlo.w, wlo.w),
                                            pk2(whi.x, whi.x), pk2(whi.y, whi.y),
                                            pk2(whi.z, whi.z), pk2(whi.w, whi.w)};
#pragma unroll
                for (int o = 0; o < 8; o++)
#pragma unroll
                    for (int p = 0; p < 4; p++)
                        acc2[o][p] = fma2(ap[p], wd[o], acc2[o][p]);
            }
        }
        __syncthreads();  // before next chunk overwrites s_wa/s_wb/s_h
    }

    // ---- cross-warp k reduce via s_h (dead now) ----
    if (khalf == 1) {
        ulonglong2* dst = (ulonglong2*)&s_h[t2 * 64];
#pragma unroll
        for (int o = 0; o < 8; o++) {
            dst[2 * o]     = make_ulonglong2(acc2[o][0], acc2[o][1]);
            dst[2 * o + 1] = make_ulonglong2(acc2[o][2], acc2[o][3]);
        }
    }
    __syncthreads();
    if (khalf == 0) {
        const ulonglong2* src = (const ulonglong2*)&s_h[t2 * 64];
#pragma unroll
        for (int o = 0; o < 8; o++) {
            ulonglong2 u0 = src[2 * o], u1 = src[2 * o + 1];
            acc2[o][0] = add2(acc2[o][0], u0.x);
            acc2[o][1] = add2(acc2[o][1], u0.y);
            acc2[o][2] = add2(acc2[o][2], u1.x);
            acc2[o][3] = add2(acc2[o][3], u1.y);
        }
        if (!FINAL) {
            // store Y1[n][row][o2..o2+7]
#pragma unroll
            for (int p = 0; p < 4; p++) {
                float2 f[8];
#pragma unroll
                for (int o = 0; o < 8; o++) f[o] = upk2(acc2[o][p]);
                size_t base = ((size_t)n * BT + rbase + r2 + 2 * p) * 8 + (o2 >> 2);
                Yout[base]     = make_float4(f[0].x, f[1].x, f[2].x, f[3].x);
                Yout[base + 1] = make_float4(f[4].x, f[5].x, f[6].x, f[7].x);
                Yout[base + 8] = make_float4(f[0].y, f[1].y, f[2].y, f[3].y);
                Yout[base + 9] = make_float4(f[4].y, f[5].y, f[6].y, f[7].y);
            }
        } else {
            // relu + transposed store out[b][n][c][t], row -> (b=row/24, t=row%24)
#pragma unroll
            for (int p = 0; p < 4; p++) {
                float2 f[8];
#pragma unroll
                for (int o = 0; o < 8; o++) f[o] = upk2(acc2[o][p]);
#pragma unroll
                for (int s = 0; s < 2; s++) {
                    int row = rbase + r2 + 2 * p + s;
                    int b = row / TT, t = row % TT;
                    size_t ob = ((size_t)(b * NN + n) * CO + o2) * TT + t;
#pragma unroll
                    for (int o = 0; o < 8; o++) {
                        float v = s ? f[o].y : f[o].x;
                        outT[ob + (size_t)o * TT] = fmaxf(v, 0.f);
                    }
                }
            }
        }
    }
}

// ---------------- launch ----------------
extern "C" void kernel_launch(void* const* d_in, const int* in_sizes, int n_in,
                              void* d_out, int out_size) {
    const float* x  = (const float*)d_in[0];
    const void*  ei = d_in[1];
    const float* W1 = (const float*)d_in[2];
    const float* b1 = (const float*)d_in[3];
    const float* W2 = (const float*)d_in[4];
    const float* b2 = (const float*)d_in[5];
    const float* W3 = (const float*)d_in[6];
    const float* b3 = (const float*)d_in[7];
    const float* W4 = (const float*)d_in[8];
    const float* b4 = (const float*)d_in[9];
    float* out = (float*)d_out;

    k_prep<<<1, 1024>>>(ei);
    k_fill<<<(NE + 255) / 256, 256>>>(ei);
    k_transpose<<<NN, 256>>>(x);
    k_gin<CI, 64, false><<<dim3(NN, 3), 64>>>(W1, b1, W2, b2, nullptr);
    k_gin<CO, 128, true><<<dim3(NN, 3), 64>>>(W3, b3, W4, b4, out);
}

// round 9
// speedup vs baseline: 1.3017x; 1.3017x over previous
#include <cuda_runtime.h>

#define NB 8
#define NN 10000
#define CI 16
#define TT 24
#define CO 32
#define NE 160000
#define BT 192   // NB*TT

// ---------------- device scratch (float4-typed => 16B alignment) ----------------
__device__ float4 g_X0[(size_t)NN * BT * CI / 4];   // 123 MB layer-1 input (node-major)
__device__ float4 g_A0[(size_t)NN * BT * CI / 4];   // 123 MB layer-1 aggregated
__device__ float4 g_Y1[(size_t)NN * BT * CO / 4];   // 246 MB layer-1 output
__device__ float4 g_A1[(size_t)NN * BT * CO / 4];   // 246 MB layer-2 aggregated
__device__ int    g_cur[NN];
__device__ int    g_rowptr[NN + 1];
__device__ int    g_col[NE];
__device__ int    g_is64;

// ---------------- packed f32x2 helpers ----------------
__device__ __forceinline__ unsigned long long fma2(unsigned long long a,
                                                   unsigned long long b,
                                                   unsigned long long c) {
    unsigned long long d;
    asm("fma.rn.f32x2 %0, %1, %2, %3;" : "=l"(d) : "l"(a), "l"(b), "l"(c));
    return d;
}
__device__ __forceinline__ unsigned long long add2(unsigned long long a,
                                                   unsigned long long b) {
    unsigned long long d;
    asm("add.rn.f32x2 %0, %1, %2;" : "=l"(d) : "l"(a), "l"(b));
    return d;
}
__device__ __forceinline__ unsigned long long pk2(float x, float y) {
    unsigned long long r;
    asm("mov.b64 %0, {%1, %2};" : "=l"(r) : "f"(x), "f"(y));
    return r;
}
__device__ __forceinline__ float2 upk2(unsigned long long a) {
    float2 r;
    asm("mov.b64 {%0, %1}, %2;" : "=f"(r.x), "=f"(r.y) : "l"(a));
    return r;
}

__device__ __forceinline__ int edge_at(const void* ei, int idx) {
    if (g_is64) return (int)((const long long*)ei)[idx];
    return ((const int*)ei)[idx];
}

// ---------------- CSR prep: dtype detect + degree histogram + scan, one block ----------------
__global__ void __launch_bounds__(1024) k_prep(const void* ei) {
    __shared__ int sdeg[NN];
    __shared__ int ssum[1024];
    int tid = threadIdx.x;
    if (tid == 0) {
        const long long* p = (const long long*)ei;
        int ok64 = 1;
        for (int q = 0; q < 64; q++) {
            long long v = p[q];
            if (v < 0 || v >= NN) { ok64 = 0; break; }
        }
        g_is64 = ok64;
    }
    __syncthreads();
    for (int i = tid; i < NN; i += 1024) sdeg[i] = 0;
    __syncthreads();
    for (int e = tid; e < NE; e += 1024) atomicAdd(&sdeg[edge_at(ei, NE + e)], 1);
    __syncthreads();
    const int CHUNK = 10;
    int start = tid * CHUNK;
    int s = 0;
    for (int i = start; i < start + CHUNK && i < NN; i++) s += sdeg[i];
    ssum[tid] = s;
    __syncthreads();
    for (int off = 1; off < 1024; off <<= 1) {
        int v = (tid >= off) ? ssum[tid - off] : 0;
        __syncthreads();
        ssum[tid] += v;
        __syncthreads();
    }
    int run = ssum[tid] - s;
    for (int i = start; i < start + CHUNK && i < NN; i++) {
        g_rowptr[i] = run;
        g_cur[i] = 0;
        run += sdeg[i];
    }
    if (tid == 1023) g_rowptr[NN] = ssum[1023];
}

__global__ void k_fill(const void* __restrict__ ei) {
    int e = blockIdx.x * blockDim.x + threadIdx.x;
    if (e < NE) {
        int srcn = edge_at(ei, e);
        int d    = edge_at(ei, NE + e);
        int p = atomicAdd(&g_cur[d], 1);
        g_col[g_rowptr[d] + p] = srcn;
    }
}

// ---------------- input transpose: x[b][n][c][t] -> X0[n][b*T+t][c] ----------------
__global__ void k_transpose(const float* __restrict__ x) {
    __shared__ float s[BT * 17];
    int n = blockIdx.x;
    for (int j = threadIdx.x; j < NB * CI * TT; j += blockDim.x) {
        int b = j / (CI * TT);
        int r = j % (CI * TT);
        int c = r / TT;
        int t = r % TT;
        s[(b * TT + t) * 17 + c] = x[((size_t)(b * NN + n)) * (CI * TT) + r];
    }
    __syncthreads();
    float* X0f = (float*)g_X0;
    for (int j = threadIdx.x; j < BT * CI; j += blockDim.x) {
        X0f[(size_t)n * (BT * CI) + j] = s[(j >> 4) * 17 + (j & 15)];
    }
}

// ================= pure gather: A[n][:] = X[n][:] + sum_src X[src][:] =================
// One float4 per thread, full occupancy, edge loop unrolled x2 (dual accumulators).
// Grid (NN, NSLAB): x-major block order keeps each y-slab's gather set L2-resident (41 MB).
template<bool L2PASS>
__global__ void __launch_bounds__(256) k_gather() {
    constexpr int NF4 = L2PASS ? (BT * CO / 4) : (BT * CI / 4);  // float4 per node
    const float4* __restrict__ Xin = L2PASS ? g_Y1 : g_X0;
    float4* __restrict__ Aout = L2PASS ? g_A1 : g_A0;

    int n = blockIdx.x;
    int j = blockIdx.y * 256 + threadIdx.x;
    size_t base = (size_t)n * NF4 + j;
    float4 acc = Xin[base];
    float4 acc2 = make_float4(0.f, 0.f, 0.f, 0.f);
    int rs = g_rowptr[n], re = g_rowptr[n + 1];
    int e = rs;
    for (; e + 1 < re; e += 2) {
        float4 v0 = Xin[(size_t)g_col[e] * NF4 + j];
        float4 v1 = Xin[(size_t)g_col[e + 1] * NF4 + j];
        acc.x += v0.x;  acc.y += v0.y;  acc.z += v0.z;  acc.w += v0.w;
        acc2.x += v1.x; acc2.y += v1.y; acc2.z += v1.z; acc2.w += v1.w;
    }
    if (e < re) {
        float4 v = Xin[(size_t)g_col[e] * NF4 + j];
        acc.x += v.x; acc.y += v.y; acc.z += v.z; acc.w += v.w;
    }
    acc.x += acc2.x; acc.y += acc2.y; acc.z += acc2.z; acc.w += acc2.w;
    Aout[base] = acc;
}

// ================= dense MLP: 64 rows/block, GEMM tiles 8x8, f32x2 =================
// Reads aggregated g_A*, writes g_Y1 (!FINAL) or transposed relu output (FINAL).
template<int KIN, int NHID, bool FINAL>
__global__ void __launch_bounds__(64) k_mlp(
    const float* __restrict__ Wa, const float* __restrict__ ba,   // [KIN][NHID], [NHID]
    const float* __restrict__ Wb, const float* __restrict__ bb,   // [NHID][32], [32]
    float* __restrict__ outT)
{
    constexpr int NCH = NHID / 64;
    constexpr int KV  = KIN / 4;
    const float4* __restrict__ Ain = FINAL ? g_A1 : g_A0;
    float4* __restrict__ Yout = g_Y1;

    __shared__ __align__(16) float s_act[KIN * 68];
    __shared__ __align__(16) float s_h[64 * 68];
    __shared__ __align__(16) float s_wa[KIN * 64];
    __shared__ __align__(16) float s_wb[64 * 32];
    __shared__ float s_ba[64];

    int tid = threadIdx.x;
    int n = blockIdx.x / 3;
    int rbase = (blockIdx.x % 3) * 64;
    size_t R0 = (size_t)blockIdx.x * 64;   // global row base (= n*BT + rbase)

    // ---- load 64 dense rows -> k-major smem ----
    {
        float4 a[KV];
        size_t ro = (R0 + tid) * KV;
#pragma unroll
        for (int q = 0; q < KV; q++) a[q] = Ain[ro + q];
#pragma unroll
        for (int q = 0; q < KV; q++) {
            s_act[(4 * q + 0) * 68 + tid] = a[q].x;
            s_act[(4 * q + 1) * 68 + tid] = a[q].y;
            s_act[(4 * q + 2) * 68 + tid] = a[q].z;
            s_act[(4 * q + 3) * 68 + tid] = a[q].w;
        }
    }

    // tile decode
    int t2 = tid & 31, khalf = tid >> 5;
    int r2 = (t2 >> 2) * 8, o2 = (t2 & 3) * 8;   // GEMM2 tile
    int r1 = (tid >> 3) * 8, j1 = (tid & 7) * 8; // GEMM1 tile

    unsigned long long acc2[8][4];
#pragma unroll
    for (int o = 0; o < 8; o++) {
        float bv = (khalf == 0) ? bb[o2 + o] : 0.f;
        unsigned long long bp = pk2(bv, bv);
#pragma unroll
        for (int p = 0; p < 4; p++) acc2[o][p] = bp;
    }

    for (int c = 0; c < NCH; c++) {
        // ---- stage chunk weights ----
        {
            const float4* Wav = (const float4*)Wa;   // [KIN][NHID/4]
            for (int i = tid; i < KIN * 16; i += 64) {
                int k = i >> 4, jv = i & 15;
                ((float4*)s_wa)[k * 16 + jv] = Wav[k * (NHID / 4) + c * 16 + jv];
            }
            const float4* Wbv = (const float4*)Wb;   // [NHID][8]
            for (int i = tid; i < 512; i += 64)
                ((float4*)s_wb)[i] = Wbv[c * 512 + i];
            s_ba[tid] = ba[c * 64 + tid];
        }
        __syncthreads();

        // ---- GEMM1: s_h[j][r] = relu(sum_k s_act[k][r]*s_wa[k][j] + ba[j]) ----
        {
            unsigned long long acc1[8][4];
#pragma unroll
            for (int o = 0; o < 8; o++) {
                float bv = s_ba[j1 + o];
                unsigned long long bp = pk2(bv, bv);
#pragma unroll
                for (int p = 0; p < 4; p++) acc1[o][p] = bp;
            }
#pragma unroll 4
            for (int k = 0; k < KIN; k++) {
                ulonglong2 a01 = *(const ulonglong2*)&s_act[k * 68 + r1];
                ulonglong2 a23 = *(const ulonglong2*)&s_act[k * 68 + r1 + 4];
                float4 wlo = *(const float4*)&s_wa[k * 64 + j1];
                float4 whi = *(const float4*)&s_wa[k * 64 + j1 + 4];
                unsigned long long ap[4] = {a01.x, a01.y, a23.x, a23.y};
                unsigned long long wd[8] = {pk2(wlo.x, wlo.x), pk2(wlo.y, wlo.y),
                                            pk2(wlo.z, wlo.z), pk2(wlo.w, wlo.w),
                                            pk2(whi.x, whi.x), pk2(whi.y, whi.y),
                                            pk2(whi.z, whi.z), pk2(whi.w, whi.w)};
#pragma unroll
                for (int o = 0; o < 8; o++)
#pragma unroll
                    for (int p = 0; p < 4; p++)
                        acc1[o][p] = fma2(ap[p], wd[o], acc1[o][p]);
            }
#pragma unroll
            for (int o = 0; o < 8; o++) {
                float2 p0 = upk2(acc1[o][0]), p1 = upk2(acc1[o][1]);
                float2 p2 = upk2(acc1[o][2]), p3 = upk2(acc1[o][3]);
                *(float4*)&s_h[(j1 + o) * 68 + r1] =
                    make_float4(fmaxf(p0.x, 0.f), fmaxf(p0.y, 0.f), fmaxf(p1.x, 0.f), fmaxf(p1.y, 0.f));
                *(float4*)&s_h[(j1 + o) * 68 + r1 + 4] =
                    make_float4(fmaxf(p2.x, 0.f), fmaxf(p2.y, 0.f), fmaxf(p3.x, 0.f), fmaxf(p3.y, 0.f));
            }
        }
        __syncthreads();

        // ---- GEMM2: acc2 += s_h[k][r] * s_wb[k][o], k split across warps ----
        {
            int k0 = khalf * 32;
#pragma unroll 4
            for (int kk = 0; kk < 32; kk++) {
                int k = k0 + kk;
                ulonglong2 a01 = *(const ulonglong2*)&s_h[k * 68 + r2];
                ulonglong2 a23 = *(const ulonglong2*)&s_h[k * 68 + r2 + 4];
                float4 wlo = *(const float4*)&s_wb[k * 32 + o2];
                float4 whi = *(const float4*)&s_wb[k * 32 + o2 + 4];
                unsigned long long ap[4] = {a01.x, a01.y, a23.x, a23.y};
                unsigned long long wd[8] = {pk2(wlo.x, wlo.x), pk2(wlo.y, wlo.y),
                                            pk2(wlo.z, wlo.z), pk2(wlo.w, wlo.w),
                                            pk2(whi.x, whi.x), pk2(whi.y, whi.y),
                                            pk2(whi.z, whi.z), pk2(whi.w, whi.w)};
#pragma unroll
                for (int o = 0; o < 8; o++)
#pragma unroll
                    for (int p = 0; p < 4; p++)
                        acc2[o][p] = fma2(ap[p], wd[o], acc2[o][p]);
            }
        }
        __syncthreads();
    }

    // ---- cross-warp k reduce via s_h (dead now) ----
    if (khalf == 1) {
        ulonglong2* dst = (ulonglong2*)&s_h[t2 * 64];
#pragma unroll
        for (int o = 0; o < 8; o++) {
            dst[2 * o]     = make_ulonglong2(acc2[o][0], acc2[o][1]);
            dst[2 * o + 1] = make_ulonglong2(acc2[o][2], acc2[o][3]);
        }
    }
    __syncthreads();
    if (khalf == 0) {
        const ulonglong2* src = (const ulonglong2*)&s_h[t2 * 64];
#pragma unroll
        for (int o = 0; o < 8; o++) {
            ulonglong2 u0 = src[2 * o], u1 = src[2 * o + 1];
            acc2[o][0] = add2(acc2[o][0], u0.x);
            acc2[o][1] = add2(acc2[o][1], u0.y);
            acc2[o][2] = add2(acc2[o][2], u1.x);
            acc2[o][3] = add2(acc2[o][3], u1.y);
        }
        if (!FINAL) {
#pragma unroll
            for (int p = 0; p < 4; p++) {
                float2 f[8];
#pragma unroll
                for (int o = 0; o < 8; o++) f[o] = upk2(acc2[o][p]);
                size_t base = (R0 + r2 + 2 * p) * 8 + (o2 >> 2);
                Yout[base]     = make_float4(f[0].x, f[1].x, f[2].x, f[3].x);
                Yout[base + 1] = make_float4(f[4].x, f[5].x, f[6].x, f[7].x);
                Yout[base + 8] = make_float4(f[0].y, f[1].y, f[2].y, f[3].y);
                Yout[base + 9] = make_float4(f[4].y, f[5].y, f[6].y, f[7].y);
            }
        } else {
#pragma unroll
            for (int p = 0; p < 4; p++) {
                float2 f[8];
#pragma unroll
                for (int o = 0; o < 8; o++) f[o] = upk2(acc2[o][p]);
#pragma unroll
                for (int s = 0; s < 2; s++) {
                    int row = rbase + r2 + 2 * p + s;
                    int b = row / TT, t = row % TT;
                    size_t ob = ((size_t)(b * NN + n) * CO + o2) * TT + t;
#pragma unroll
                    for (int o = 0; o < 8; o++) {
                        float v = s ? f[o].y : f[o].x;
                        outT[ob + (size_t)o * TT] = fmaxf(v, 0.f);
                    }
                }
            }
        }
    }
}

// ---------------- launch ----------------
extern "C" void kernel_launch(void* const* d_in, const int* in_sizes, int n_in,
                              void* d_out, int out_size) {
    const float* x  = (const float*)d_in[0];
    const void*  ei = d_in[1];
    const float* W1 = (const float*)d_in[2];
    const float* b1 = (const float*)d_in[3];
    const float* W2 = (const float*)d_in[4];
    const float* b2 = (const float*)d_in[5];
    const float* W3 = (const float*)d_in[6];
    const float* b3 = (const float*)d_in[7];
    const float* W4 = (const float*)d_in[8];
    const float* b4 = (const float*)d_in[9];
    float* out = (float*)d_out;

    k_prep<<<1, 1024>>>(ei);
    k_fill<<<(NE + 255) / 256, 256>>>(ei);
    k_transpose<<<NN, 256>>>(x);
    k_gather<false><<<dim3(NN, 3), 256>>>();
    k_mlp<CI, 64, false><<<NN * 3, 64>>>(W1, b1, W2, b2, nullptr);
    k_gather<true><<<dim3(NN, 6), 256>>>();
    k_mlp<CO, 128, true><<<NN * 3, 64>>>(W3, b3, W4, b4, out);
}

// round 10
// speedup vs baseline: 1.3904x; 1.0682x over previous
#include <cuda_runtime.h>

#define NB 8
#define NN 10000
#define CI 16
#define TT 24
#define CO 32
#define NE 160000
#define BT 192   // NB*TT

// ---------------- device scratch (float4-typed => 16B alignment) ----------------
__device__ float4 g_X0[(size_t)NN * BT * CI / 4];   // 123 MB layer-1 input (node-major)
__device__ float4 g_A0[(size_t)NN * BT * CI / 4];   // 123 MB layer-1 aggregated
__device__ float4 g_Y1[(size_t)NN * BT * CO / 4];   // 246 MB layer-1 output
__device__ float4 g_A1[(size_t)NN * BT * CO / 4];   // 246 MB layer-2 aggregated
__device__ int    g_rowptr[NN + 1];
__device__ int    g_col[NE];
__device__ int    g_is64;

// ---------------- packed f32x2 helpers ----------------
__device__ __forceinline__ unsigned long long fma2(unsigned long long a,
                                                   unsigned long long b,
                                                   unsigned long long c) {
    unsigned long long d;
    asm("fma.rn.f32x2 %0, %1, %2, %3;" : "=l"(d) : "l"(a), "l"(b), "l"(c));
    return d;
}
__device__ __forceinline__ unsigned long long add2(unsigned long long a,
                                                   unsigned long long b) {
    unsigned long long d;
    asm("add.rn.f32x2 %0, %1, %2;" : "=l"(d) : "l"(a), "l"(b));
    return d;
}
__device__ __forceinline__ unsigned long long pk2(float x, float y) {
    unsigned long long r;
    asm("mov.b64 %0, {%1, %2};" : "=l"(r) : "f"(x), "f"(y));
    return r;
}
__device__ __forceinline__ float2 upk2(unsigned long long a) {
    float2 r;
    asm("mov.b64 {%0, %1}, %2;" : "=f"(r.x), "=f"(r.y) : "l"(a));
    return r;
}

__device__ __forceinline__ int edge_at(const void* ei, int idx) {
    if (g_is64) return (int)((const long long*)ei)[idx];
    return ((const int*)ei)[idx];
}

// ---------------- CSR prep+fill: detect + histogram + scan + fill, ONE block ----------------
__global__ void __launch_bounds__(1024) k_prepfill(const void* ei) {
    __shared__ int sdeg[NN];    // degree, then reused as fill cursor
    __shared__ int ssum[1024];
    int tid = threadIdx.x;
    if (tid == 0) {  // int64 indices all in [0,NN); int32-reinterpreted are not
        const long long* p = (const long long*)ei;
        int ok64 = 1;
        for (int q = 0; q < 64; q++) {
            long long v = p[q];
            if (v < 0 || v >= NN) { ok64 = 0; break; }
        }
        g_is64 = ok64;
    }
    __syncthreads();
    for (int i = tid; i < NN; i += 1024) sdeg[i] = 0;
    __syncthreads();
    for (int e = tid; e < NE; e += 1024) atomicAdd(&sdeg[edge_at(ei, NE + e)], 1);
    __syncthreads();
    const int CHUNK = 10;  // 1024*10 >= NN
    int start = tid * CHUNK;
    int s = 0;
    for (int i = start; i < start + CHUNK && i < NN; i++) s += sdeg[i];
    ssum[tid] = s;
    __syncthreads();
    for (int off = 1; off < 1024; off <<= 1) {
        int v = (tid >= off) ? ssum[tid - off] : 0;
        __syncthreads();
        ssum[tid] += v;
        __syncthreads();
    }
    int run = ssum[tid] - s;
    for (int i = start; i < start + CHUNK && i < NN; i++) {
        g_rowptr[i] = run;
        run += sdeg[i];
    }
    if (tid == 1023) g_rowptr[NN] = ssum[1023];
    __syncthreads();                       // scan reads of sdeg done
    for (int i = tid; i < NN; i += 1024) sdeg[i] = 0;   // now cursors
    __syncthreads();                       // g_rowptr writes + cursors visible
    for (int e = tid; e < NE; e += 1024) {
        int srcn = edge_at(ei, e);
        int d    = edge_at(ei, NE + e);
        int p = atomicAdd(&sdeg[d], 1);
        g_col[g_rowptr[d] + p] = srcn;
    }
}

// ---------------- input transpose: x[b][n][c][t] -> X0[n][b*T+t][c] ----------------
__global__ void k_transpose(const float* __restrict__ x) {
    __shared__ float s[BT * 17];
    int n = blockIdx.x;
    for (int j = threadIdx.x; j < NB * CI * TT; j += blockDim.x) {
        int b = j / (CI * TT);
        int r = j % (CI * TT);
        int c = r / TT;
        int t = r % TT;
        s[(b * TT + t) * 17 + c] = x[((size_t)(b * NN + n)) * (CI * TT) + r];
    }
    __syncthreads();
    float* X0f = (float*)g_X0;
    for (int j = threadIdx.x; j < BT * CI; j += blockDim.x) {
        X0f[(size_t)n * (BT * CI) + j] = s[(j >> 4) * 17 + (j & 15)];
    }
}

// ================= pure gather: A[n][:] = X[n][:] + sum_src X[src][:] =================
template<bool L2PASS>
__global__ void __launch_bounds__(256) k_gather() {
    constexpr int NF4 = L2PASS ? (BT * CO / 4) : (BT * CI / 4);
    const float4* __restrict__ Xin = L2PASS ? g_Y1 : g_X0;
    float4* __restrict__ Aout = L2PASS ? g_A1 : g_A0;

    int n = blockIdx.x;
    int j = blockIdx.y * 256 + threadIdx.x;
    size_t base = (size_t)n * NF4 + j;
    float4 acc = Xin[base];
    float4 acc2 = make_float4(0.f, 0.f, 0.f, 0.f);
    int rs = g_rowptr[n], re = g_rowptr[n + 1];
    int e = rs;
    for (; e + 1 < re; e += 2) {
        float4 v0 = Xin[(size_t)g_col[e] * NF4 + j];
        float4 v1 = Xin[(size_t)g_col[e + 1] * NF4 + j];
        acc.x += v0.x;  acc.y += v0.y;  acc.z += v0.z;  acc.w += v0.w;
        acc2.x += v1.x; acc2.y += v1.y; acc2.z += v1.z; acc2.w += v1.w;
    }
    if (e < re) {
        float4 v = Xin[(size_t)g_col[e] * NF4 + j];
        acc.x += v.x; acc.y += v.y; acc.z += v.z; acc.w += v.w;
    }
    acc.x += acc2.x; acc.y += acc2.y; acc.z += acc2.z; acc.w += acc2.w;
    Aout[base] = acc;
}

// ================= dense MLP: 64 rows/block, 128 threads (4 warps -> all SMSPs) =================
// GEMM1 tile 8r x 4o (16 rgrp x 16 jgrp), GEMM2 k-split 2 x (8r x 4o).
template<int KIN, int NHID, bool FINAL>
__global__ void __launch_bounds__(128) k_mlp(
    const float* __restrict__ Wa, const float* __restrict__ ba,   // [KIN][NHID], [NHID]
    const float* __restrict__ Wb, const float* __restrict__ bb,   // [NHID][32], [32]
    float* __restrict__ outT)
{
    constexpr int NCH = NHID / 64;
    constexpr int KV  = KIN / 4;
    constexpr int KVH = KV / 2;
    const float4* __restrict__ Ain = FINAL ? g_A1 : g_A0;
    float4* __restrict__ Yout = g_Y1;

    __shared__ __align__(16) float s_act[KIN * 68];
    __shared__ __align__(16) float s_h[64 * 68];
    __shared__ __align__(16) float s_wa[KIN * 64];
    __shared__ __align__(16) float s_wb[64 * 32];
    __shared__ float s_ba[64];

    int tid = threadIdx.x;
    int n = blockIdx.x / 3;
    int rbase = (blockIdx.x % 3) * 64;
    size_t R0 = (size_t)blockIdx.x * 64;   // global row base

    // ---- load 64 rows (2 threads/row) -> k-major smem ----
    {
        int row = tid >> 1, half = tid & 1;
        float4 a[KVH];
        size_t ro = (R0 + row) * KV + half * KVH;
#pragma unroll
        for (int q = 0; q < KVH; q++) a[q] = Ain[ro + q];
#pragma unroll
        for (int q = 0; q < KVH; q++) {
            int k4 = half * KVH + q;
            s_act[(4 * k4 + 0) * 68 + row] = a[q].x;
            s_act[(4 * k4 + 1) * 68 + row] = a[q].y;
            s_act[(4 * k4 + 2) * 68 + row] = a[q].z;
            s_act[(4 * k4 + 3) * 68 + row] = a[q].w;
        }
    }

    // tile decode
    int r1 = (tid >> 4) * 8, j1 = (tid & 15) * 4;    // GEMM1
    int khalf = tid >> 6, t2 = tid & 63;
    int r2 = (t2 >> 3) * 8, o2 = (t2 & 7) * 4;       // GEMM2

    unsigned long long acc2[4][4];
#pragma unroll
    for (int o = 0; o < 4; o++) {
        float bv = (khalf == 0) ? bb[o2 + o] : 0.f;
        unsigned long long bp = pk2(bv, bv);
#pragma unroll
        for (int p = 0; p < 4; p++) acc2[o][p] = bp;
    }

    for (int c = 0; c < NCH; c++) {
        // ---- stage chunk weights ----
        {
            const float4* Wav = (const float4*)Wa;   // [KIN][NHID/4]
            for (int i = tid; i < KIN * 16; i += 128) {
                int k = i >> 4, jv = i & 15;
                ((float4*)s_wa)[k * 16 + jv] = Wav[k * (NHID / 4) + c * 16 + jv];
            }
            const float4* Wbv = (const float4*)Wb;   // [NHID][8]
            for (int i = tid; i < 512; i += 128)
                ((float4*)s_wb)[i] = Wbv[c * 512 + i];
            if (tid < 64) s_ba[tid] = ba[c * 64 + tid];
        }
        __syncthreads();

        // ---- GEMM1: s_h[j][r] = relu(sum_k act*W + b) ----
        {
            unsigned long long acc1[4][4];
#pragma unroll
            for (int o = 0; o < 4; o++) {
                float bv = s_ba[j1 + o];
                unsigned long long bp = pk2(bv, bv);
#pragma unroll
                for (int p = 0; p < 4; p++) acc1[o][p] = bp;
            }
#pragma unroll 4
            for (int k = 0; k < KIN; k++) {
                ulonglong2 a01 = *(const ulonglong2*)&s_act[k * 68 + r1];
                ulonglong2 a23 = *(const ulonglong2*)&s_act[k * 68 + r1 + 4];
                float4 w = *(const float4*)&s_wa[k * 64 + j1];
                unsigned long long ap[4] = {a01.x, a01.y, a23.x, a23.y};
                unsigned long long wd[4] = {pk2(w.x, w.x), pk2(w.y, w.y),
                                            pk2(w.z, w.z), pk2(w.w, w.w)};
#pragma unroll
                for (int o = 0; o < 4; o++)
#pragma unroll
                    for (int p = 0; p < 4; p++)
                        acc1[o][p] = fma2(ap[p], wd[o], acc1[o][p]);
            }
#pragma unroll
            for (int o = 0; o < 4; o++) {
                float2 p0 = upk2(acc1[o][0]), p1 = upk2(acc1[o][1]);
                float2 p2 = upk2(acc1[o][2]), p3 = upk2(acc1[o][3]);
                *(float4*)&s_h[(j1 + o) * 68 + r1] =
                    make_float4(fmaxf(p0.x, 0.f), fmaxf(p0.y, 0.f), fmaxf(p1.x, 0.f), fmaxf(p1.y, 0.f));
                *(float4*)&s_h[(j1 + o) * 68 + r1 + 4] =
                    make_float4(fmaxf(p2.x, 0.f), fmaxf(p2.y, 0.f), fmaxf(p3.x, 0.f), fmaxf(p3.y, 0.f));
            }
        }
        __syncthreads();

        // ---- GEMM2: acc2 += s_h[k][r] * s_wb[k][o], k split across thread-halves ----
        {
            int k0 = khalf * 32;
#pragma unroll 4
            for (int kk = 0; kk < 32; kk++) {
                int k = k0 + kk;
                ulonglong2 a01 = *(const ulonglong2*)&s_h[k * 68 + r2];
                ulonglong2 a23 = *(const ulonglong2*)&s_h[k * 68 + r2 + 4];
                float4 w = *(const float4*)&s_wb[k * 32 + o2];
                unsigned long long ap[4] = {a01.x, a01.y, a23.x, a23.y};
                unsigned long long wd[4] = {pk2(w.x, w.x), pk2(w.y, w.y),
                                            pk2(w.z, w.z), pk2(w.w, w.w)};
#pragma unroll
                for (int o = 0; o < 4; o++)
#pragma unroll
                    for (int p = 0; p < 4; p++)
                        acc2[o][p] = fma2(ap[p], wd[o], acc2[o][p]);
            }
        }
        __syncthreads();
    }

    // ---- cross-half k reduce via s_h (dead now) ----
    if (khalf == 1) {
        ulonglong2* dst = (ulonglong2*)&s_h[t2 * 32];
#pragma unroll
        for (int o = 0; o < 4; o++) {
            dst[2 * o]     = make_ulonglong2(acc2[o][0], acc2[o][1]);
            dst[2 * o + 1] = make_ulonglong2(acc2[o][2], acc2[o][3]);
        }
    }
    __syncthreads();
    if (khalf == 0) {
        const ulonglong2* src = (const ulonglong2*)&s_h[t2 * 32];
#pragma unroll
        for (int o = 0; o < 4; o++) {
            ulonglong2 u0 = src[2 * o], u1 = src[2 * o + 1];
            acc2[o][0] = add2(acc2[o][0], u0.x);
            acc2[o][1] = add2(acc2[o][1], u0.y);
            acc2[o][2] = add2(acc2[o][2], u1.x);
            acc2[o][3] = add2(acc2[o][3], u1.y);
        }
        if (!FINAL) {
#pragma unroll
            for (int p = 0; p < 4; p++) {
                float2 f[4];
#pragma unroll
                for (int o = 0; o < 4; o++) f[o] = upk2(acc2[o][p]);
                size_t base = (R0 + r2 + 2 * p) * 8 + (o2 >> 2);
                Yout[base]     = make_float4(f[0].x, f[1].x, f[2].x, f[3].x);
                Yout[base + 8] = make_float4(f[0].y, f[1].y, f[2].y, f[3].y);
            }
        } else {
#pragma unroll
            for (int p = 0; p < 4; p++) {
                float2 f[4];
#pragma unroll
                for (int o = 0; o < 4; o++) f[o] = upk2(acc2[o][p]);
#pragma unroll
                for (int s = 0; s < 2; s++) {
                    int row = rbase + r2 + 2 * p + s;
                    int b = row / TT, t = row % TT;
                    size_t ob = ((size_t)(b * NN + n) * CO + o2) * TT + t;
#pragma unroll
                    for (int o = 0; o < 4; o++) {
                        float v = s ? f[o].y : f[o].x;
                        outT[ob + (size_t)o * TT] = fmaxf(v, 0.f);
                    }
                }
            }
        }
    }
}

// ---------------- launch ----------------
extern "C" void kernel_launch(void* const* d_in, const int* in_sizes, int n_in,
                              void* d_out, int out_size) {
    const float* x  = (const float*)d_in[0];
    const void*  ei = d_in[1];
    const float* W1 = (const float*)d_in[2];
    const float* b1 = (const float*)d_in[3];
    const float* W2 = (const float*)d_in[4];
    const float* b2 = (const float*)d_in[5];
    const float* W3 = (const float*)d_in[6];
    const float* b3 = (const float*)d_in[7];
    const float* W4 = (const float*)d_in[8];
    const float* b4 = (const float*)d_in[9];
    float* out = (float*)d_out;

    k_prepfill<<<1, 1024>>>(ei);
    k_transpose<<<NN, 256>>>(x);
    k_gather<false><<<dim3(NN, 3), 256>>>();
    k_mlp<CI, 64, false><<<NN * 3, 128>>>(W1, b1, W2, b2, nullptr);
    k_gather<true><<<dim3(NN, 6), 256>>>();
    k_mlp<CO, 128, true><<<NN * 3, 128>>>(W3, b3, W4, b4, out);
}